// round 15
// baseline (speedup 1.0000x reference)
#include <cuda_runtime.h>
#include <cuda_fp16.h>
#include <math.h>
#include <stdint.h>

// Problem constants
#define T_TOKENS 8192
#define D_DIM    1024
#define H_DIM    4096
#define R_DIM    512
#define E_NUM    8
#define SLOTS    (T_TOKENS * 2)
#define MAX_TILES 136
#define KR_DIM   3072   // router split-K: [xh|xh|xl] x [wh|wl|wh]
#define SEG_CAP  16384  // fixed per-expert perm segment
#define UP_CTAS  (MAX_TILES * 32)   // 4352
#define DN_CTAS  (MAX_TILES * 8)    // 1088

// ---------------- scratch (device globals; no allocation allowed) ----------
__device__ __half g_xsplit[T_TOKENS * KR_DIM];       // [xh|xh|xl]      50MB
__device__ __half g_wr1split[R_DIM * KR_DIM];        // [wh|wl|wh]*32    3MB
__device__ __half g_W1h[E_NUM * H_DIM * D_DIM];      // W1 fp16         67MB
__device__ __half g_W2h[E_NUM * D_DIM * H_DIM];      // W2 fp16         67MB
__device__ __half g_He[SLOTS * H_DIM];               // expert hidden  134MB
__device__ float  g_logits[T_TOKENS * E_NUM];
__device__ float  g_expW[SLOTS];
__device__ int    g_rowdone[64];
__device__ int    g_fillpos[E_NUM];
__device__ int    g_perm[E_NUM * SEG_CAP];
__device__ int    g_mtdone[MAX_TILES];               // UP n-tiles done per mt

__device__ __forceinline__ float gelu_exact(float x) {
    return 0.5f * x * (1.0f + erff(x * 0.7071067811865476f));
}

__device__ __forceinline__ uint32_t smem_to_u32(const void* p) {
    uint32_t a;
    asm("{ .reg .u64 t; cvta.to.shared.u64 t, %1; cvt.u32.u64 %0, t; }" : "=r"(a) : "l"(p));
    return a;
}
#define CP_ASYNC16(dst, src, sz) \
    asm volatile("cp.async.cg.shared.global [%0], [%1], 16, %2;" \
                 :: "r"(dst), "l"(src), "r"(sz))
#define CP_COMMIT() asm volatile("cp.async.commit_group;" ::: "memory")
#define CP_WAIT1()  asm volatile("cp.async.wait_group 1;" ::: "memory")

#define LDSM_X4(r0, r1, r2, r3, addr) \
    asm volatile("ldmatrix.sync.aligned.m8n8.x4.shared.b16 {%0,%1,%2,%3}, [%4];" \
                 : "=r"(r0), "=r"(r1), "=r"(r2), "=r"(r3) : "r"(addr))

// ---------------- fused converts --------------------------------------------
__global__ void conv_kernel(const float* __restrict__ W1,
                            const float* __restrict__ W2, int n4) {
    int i = blockIdx.x * blockDim.x + threadIdx.x;
    const float* src;
    __half* dst;
    if (i < n4) { src = W1; dst = g_W1h; }
    else        { i -= n4; src = W2; dst = g_W2h; }
    float4 v = reinterpret_cast<const float4*>(src)[i];
    __half2* d2 = reinterpret_cast<__half2*>(dst + (size_t)i * 4);
    d2[0] = __floats2half2_rn(v.x, v.y);
    d2[1] = __floats2half2_rn(v.z, v.w);
}

// zero d_out (poisoned 0xAA; fused DOWN epilogue accumulates into it)
__global__ void zero_out_kernel(float* __restrict__ out) {
    int i = blockIdx.x * blockDim.x + threadIdx.x;
    reinterpret_cast<float4*>(out)[i] = make_float4(0.f, 0.f, 0.f, 0.f);
}

// x -> [xh|xh|xl], Wr1*32 -> [wh|wl|wh]; zeroes logits/rowdone/fillpos/mtdone
__global__ void split_kernel(const float* __restrict__ x,
                             const float* __restrict__ w) {
    if (blockIdx.x < 64) {
        int zi = blockIdx.x * 256 + threadIdx.x;
        reinterpret_cast<float4*>(g_logits)[zi] = make_float4(0.f, 0.f, 0.f, 0.f);
    } else if (blockIdx.x == 64) {
        int t = threadIdx.x;
        if (t < 64) g_rowdone[t] = 0;
        else if (t < 64 + E_NUM) g_fillpos[t - 64] = 0;
        else if (t < 72 + MAX_TILES) g_mtdone[t - 72] = 0;
    }
    int i = blockIdx.x * blockDim.x + threadIdx.x;
    int row = i >> 8;
    int c4 = (i & 255) * 4;
    __half h[4], l[4];
    if (row < T_TOKENS) {
        float4 v = reinterpret_cast<const float4*>(x)[i];
        float vv[4] = {v.x, v.y, v.z, v.w};
#pragma unroll
        for (int q = 0; q < 4; q++) {
            h[q] = __float2half_rn(vv[q]);
            l[q] = __float2half_rn(vv[q] - __half2float(h[q]));
        }
        __half* r = g_xsplit + (size_t)row * KR_DIM + c4;
        __half2 h01 = __halves2half2(h[0], h[1]), h23 = __halves2half2(h[2], h[3]);
        __half2 l01 = __halves2half2(l[0], l[1]), l23 = __halves2half2(l[2], l[3]);
        ((__half2*)(r))[0] = h01;        ((__half2*)(r))[1] = h23;
        ((__half2*)(r + 1024))[0] = h01; ((__half2*)(r + 1024))[1] = h23;
        ((__half2*)(r + 2048))[0] = l01; ((__half2*)(r + 2048))[1] = l23;
    } else {
        int wr = row - T_TOKENS;
        float4 v = reinterpret_cast<const float4*>(w)[(size_t)wr * 256 + (c4 >> 2)];
        float vv[4] = {v.x * 32.f, v.y * 32.f, v.z * 32.f, v.w * 32.f};
#pragma unroll
        for (int q = 0; q < 4; q++) {
            h[q] = __float2half_rn(vv[q]);
            l[q] = __float2half_rn(vv[q] - __half2float(h[q]));
        }
        __half* r = g_wr1split + (size_t)wr * KR_DIM + c4;
        __half2 h01 = __halves2half2(h[0], h[1]), h23 = __halves2half2(h[2], h[3]);
        __half2 l01 = __halves2half2(l[0], l[1]), l23 = __halves2half2(l[2], l[3]);
        ((__half2*)(r))[0] = h01;        ((__half2*)(r))[1] = h23;
        ((__half2*)(r + 1024))[0] = l01; ((__half2*)(r + 1024))[1] = l23;
        ((__half2*)(r + 2048))[0] = h01; ((__half2*)(r + 2048))[1] = h23;
    }
}

// ---------------- shared tiling constants ------------------------------------
#define OFF_STAGE  8192
#define STAGE_BYTES 32768
#define SMEM_TOTAL (OFF_STAGE + 3 * STAGE_BYTES)

// ---------------- router GEMM (fused logits/top2/fill) ------------------------
__global__ void __launch_bounds__(256, 2) router_gemm_kernel(
    const float* __restrict__ br1,
    const float* __restrict__ Wr2,
    const float* __restrict__ br2)
{
    constexpr int NITER = KR_DIM / 64;

    extern __shared__ char smem[];
    __shared__ int sOld;
    const uint32_t sb = smem_to_u32(smem);
    float* sW2 = (float*)smem;
    const int tid = threadIdx.x;
    const int wid = tid >> 5;
    const int lane = tid & 31;
    const int n0 = blockIdx.x * 128;
    const int m0 = blockIdx.y * 128;

    {
        int f = tid * 4;
        int e = f >> 7;
        int j = f & 127;
        float4 v = *reinterpret_cast<const float4*>(&Wr2[e * R_DIM + n0 + j]);
        *reinterpret_cast<float4*>(&sW2[f]) = v;
    }
    __syncthreads();

    auto load_stage = [&](int it) {
        const uint32_t so = sb + OFF_STAGE + (uint32_t)(it % 3) * STAGE_BYTES;
        const size_t kb = (size_t)it * 128;
#pragma unroll
        for (int j = 0; j < 4; j++) {
            int c = tid + j * 256;
            int r = c >> 3;
            int kc = (c & 7) << 4;
            uint32_t dst = so + (uint32_t)(r * 128 + (kc ^ ((r & 7) << 4)));
            const char* src = (const char*)(g_xsplit + (size_t)(m0 + r) * KR_DIM) + kb + kc;
            CP_ASYNC16(dst, src, 16u);
        }
#pragma unroll
        for (int j = 0; j < 4; j++) {
            int c = tid + j * 256;
            int r = c >> 3;
            int kc = (c & 7) << 4;
            uint32_t dst = so + 16384u + (uint32_t)(r * 128 + (kc ^ ((r & 7) << 4)));
            const char* src = (const char*)(g_wr1split + (size_t)(n0 + r) * KR_DIM) + kb + kc;
            CP_ASYNC16(dst, src, 16u);
        }
    };

    const int wm = (wid & 1) * 64;
    const int wn = (wid >> 1) * 32;
    const uint32_t sw = (uint32_t)((lane & 7) << 4);

    float acc[4][4][4];
#pragma unroll
    for (int i = 0; i < 4; i++)
#pragma unroll
        for (int j = 0; j < 4; j++)
#pragma unroll
            for (int k = 0; k < 4; k++) acc[i][j][k] = 0.f;

    uint32_t aBase[4], bBase[2];
#pragma unroll
    for (int mf = 0; mf < 4; mf++) {
        int r = wm + mf * 16 + (lane & 15);
        aBase[mf] = (uint32_t)(r * 128) + ((uint32_t)((lane >> 4) << 4) ^ sw);
    }
#pragma unroll
    for (int np = 0; np < 2; np++) {
        int r = wn + np * 16 + ((lane >> 4) << 3) + (lane & 7);
        bBase[np] = (uint32_t)(r * 128 + 16384) + ((uint32_t)(((lane >> 3) & 1) << 4) ^ sw);
    }

    load_stage(0);
    CP_COMMIT();
    load_stage(1);
    CP_COMMIT();

    for (int it = 0; it < NITER; ++it) {
        CP_WAIT1();
        __syncthreads();
        if (it + 2 < NITER) load_stage(it + 2);
        CP_COMMIT();

        const uint32_t stg = sb + OFF_STAGE + (uint32_t)(it % 3) * STAGE_BYTES;

        uint32_t af[2][4][4];
        uint32_t bf[2][4][2];
#pragma unroll
        for (int mf = 0; mf < 4; mf++)
            LDSM_X4(af[0][mf][0], af[0][mf][1], af[0][mf][2], af[0][mf][3],
                    stg + aBase[mf]);
#pragma unroll
        for (int np = 0; np < 2; np++)
            LDSM_X4(bf[0][2 * np][0], bf[0][2 * np][1],
                    bf[0][2 * np + 1][0], bf[0][2 * np + 1][1],
                    stg + bBase[np]);

#pragma unroll
        for (int ks = 0; ks < 4; ks++) {
            const int cur = ks & 1;
            const int nxt = cur ^ 1;
            if (ks < 3) {
                const uint32_t x = (uint32_t)((ks + 1) << 5);
#pragma unroll
                for (int mf = 0; mf < 4; mf++)
                    LDSM_X4(af[nxt][mf][0], af[nxt][mf][1], af[nxt][mf][2], af[nxt][mf][3],
                            stg + (aBase[mf] ^ x));
#pragma unroll
                for (int np = 0; np < 2; np++)
                    LDSM_X4(bf[nxt][2 * np][0], bf[nxt][2 * np][1],
                            bf[nxt][2 * np + 1][0], bf[nxt][2 * np + 1][1],
                            stg + (bBase[np] ^ x));
            }
#pragma unroll
            for (int mf = 0; mf < 4; mf++)
#pragma unroll
                for (int nf = 0; nf < 4; nf++) {
                    asm volatile(
                        "mma.sync.aligned.m16n8k16.row.col.f32.f16.f16.f32 "
                        "{%0,%1,%2,%3}, {%4,%5,%6,%7}, {%8,%9}, {%0,%1,%2,%3};"
                        : "+f"(acc[mf][nf][0]), "+f"(acc[mf][nf][1]),
                          "+f"(acc[mf][nf][2]), "+f"(acc[mf][nf][3])
                        : "r"(af[cur][mf][0]), "r"(af[cur][mf][1]),
                          "r"(af[cur][mf][2]), "r"(af[cur][mf][3]),
                          "r"(bf[cur][nf][0]), "r"(bf[cur][nf][1]));
                }
        }
    }

    const int lr = lane >> 2;
    const int lc = (lane & 3) * 2;
#pragma unroll
    for (int mf = 0; mf < 4; mf++) {
#pragma unroll
        for (int h = 0; h < 2; h++) {
            int rl = wm + mf * 16 + lr + h * 8;
            float part[E_NUM];
#pragma unroll
            for (int e = 0; e < E_NUM; e++) part[e] = 0.f;
#pragma unroll
            for (int nf = 0; nf < 4; nf++) {
                int colL = wn + nf * 8 + lc;
                float v0 = gelu_exact(acc[mf][nf][h * 2 + 0] * 0.03125f + br1[n0 + colL]);
                float v1 = gelu_exact(acc[mf][nf][h * 2 + 1] * 0.03125f + br1[n0 + colL + 1]);
#pragma unroll
                for (int e = 0; e < E_NUM; e++)
                    part[e] += v0 * sW2[e * 128 + colL] + v1 * sW2[e * 128 + colL + 1];
            }
#pragma unroll
            for (int e = 0; e < E_NUM; e++) {
                part[e] += __shfl_xor_sync(0xffffffffu, part[e], 1);
                part[e] += __shfl_xor_sync(0xffffffffu, part[e], 2);
            }
            if ((lane & 3) == 0) {
#pragma unroll
                for (int e = 0; e < E_NUM; e++)
                    atomicAdd(&g_logits[(size_t)(m0 + rl) * E_NUM + e], part[e]);
            }
        }
    }
    __syncthreads();
    if (tid == 0) {
        __threadfence();
        sOld = atomicAdd(&g_rowdone[blockIdx.y], 1);
    }
    __syncthreads();
    if (sOld == 3 && tid < 128) {
        __threadfence();
        int t = m0 + tid;
        float l[E_NUM];
#pragma unroll
        for (int e = 0; e < E_NUM; e++)
            l[e] = __ldcg(&g_logits[(size_t)t * E_NUM + e]) + br2[e];
        int i0 = 0; float v0 = l[0];
#pragma unroll
        for (int e = 1; e < E_NUM; e++) if (l[e] > v0) { v0 = l[e]; i0 = e; }
        int i1 = -1; float v1 = -1e30f;
#pragma unroll
        for (int e = 0; e < E_NUM; e++) if (e != i0 && l[e] > v1) { v1 = l[e]; i1 = e; }
        float s = 0.f;
#pragma unroll
        for (int e = 0; e < E_NUM; e++) s += expf(l[e] - v0);
        g_expW[2 * t]     = 1.f / s;
        g_expW[2 * t + 1] = expf(v1 - v0) / s;
        int r0 = atomicAdd(&g_fillpos[i0], 1);
        g_perm[i0 * SEG_CAP + r0] = 2 * t;
        int r1 = atomicAdd(&g_fillpos[i1], 1);
        g_perm[i1 * SEG_CAP + r1] = 2 * t + 1;
    }
}

// ---------------- fused expert UP+DOWN kernel ---------------------------------
// bids [0, UP_CTAS):  UP tile  (mt = bid>>5, n0 = (bid&31)<<7)
//      He = gelu(xh@W1[e]^T + b1[e]); epilogue increments g_mtdone[mt]
// bids [UP_CTAS, +DN): DOWN tile (mt = r>>3, n0 = (r&7)<<7)
//      spin until g_mtdone[mt]==32, then out[token] += w_slot*(He@W2[e]^T+b2)
// Dispatch is bid-ordered, so all UP CTAs are dispatched before any DOWN CTA
// starts -> spin always terminates (no deadlock).
__global__ void __launch_bounds__(256, 2) expert_fused_kernel(
    const float* __restrict__ b1,
    const float* __restrict__ b2,
    float* __restrict__ outp)
{
    const int bid = blockIdx.x;
    const bool isUp = bid < UP_CTAS;
    const int mt = isUp ? (bid >> 5) : ((bid - UP_CTAS) >> 3);
    const int n0 = isUp ? ((bid & 31) << 7) : (((bid - UP_CTAS) & 7) << 7);
    const int K_DIM = isUp ? 1024 : 4096;
    const int A_STRIDE = isUp ? KR_DIM : 4096;
    const int NITER = K_DIM >> 6;

    extern __shared__ char smem[];
    const uint32_t sb = smem_to_u32(smem);
    int* sSlot = (int*)smem;
    const int tid = threadIdx.x;
    const int wid = tid >> 5;
    const int lane = tid & 31;

    // tile map from g_fillpos
    int eIdx = -1;
    int pos0 = 0, segEnd = 0, tS = 0;
#pragma unroll
    for (int e = 0; e < E_NUM; e++) {
        int cnt = g_fillpos[e];
        int tiles = (cnt + 127) >> 7;
        if (eIdx < 0 && mt >= tS && mt < tS + tiles) {
            eIdx = e;
            pos0 = e * SEG_CAP + (mt - tS) * 128;
            segEnd = e * SEG_CAP + cnt;
        }
        tS += tiles;
    }
    if (eIdx < 0) return;   // phantom tile (no counter action either side)

    if (!isUp) {
        // wait for all 32 UP n-tiles of this mt
        if (tid == 0) {
            while (*(volatile int*)&g_mtdone[mt] < 32) __nanosleep(64);
        }
        __syncthreads();
        __threadfence();    // acquire: order He reads after counter observation
    }

    if (tid < 128) {
        int p = pos0 + tid;
        sSlot[tid] = (p < segEnd) ? g_perm[p] : -1;
    }
    __syncthreads();

    const __half* Abase = isUp ? g_xsplit : g_He;
    const __half* Bbase = isUp ? (g_W1h + (size_t)eIdx * (H_DIM * D_DIM))
                               : (g_W2h + (size_t)eIdx * (D_DIM * H_DIM));
    const float* bptr = isUp ? (b1 + eIdx * H_DIM) : (b2 + eIdx * D_DIM);

    int aRow[4];
    uint32_t aSz[4];
#pragma unroll
    for (int j = 0; j < 4; j++) {
        int r = (tid + j * 256) >> 3;
        int slot = sSlot[r];
        if (slot < 0) { aRow[j] = 0; aSz[j] = 0; }
        else { aRow[j] = isUp ? (slot >> 1) : slot; aSz[j] = 16; }
    }

    auto load_stage = [&](int it) {
        const uint32_t so = sb + OFF_STAGE + (uint32_t)(it % 3) * STAGE_BYTES;
        const size_t kb = (size_t)it * 128;
#pragma unroll
        for (int j = 0; j < 4; j++) {
            int c = tid + j * 256;
            int r = c >> 3;
            int kc = (c & 7) << 4;
            uint32_t dst = so + (uint32_t)(r * 128 + (kc ^ ((r & 7) << 4)));
            const char* src = (const char*)(Abase + (size_t)aRow[j] * A_STRIDE) + kb + kc;
            CP_ASYNC16(dst, src, aSz[j]);
        }
#pragma unroll
        for (int j = 0; j < 4; j++) {
            int c = tid + j * 256;
            int r = c >> 3;
            int kc = (c & 7) << 4;
            uint32_t dst = so + 16384u + (uint32_t)(r * 128 + (kc ^ ((r & 7) << 4)));
            const char* src = (const char*)(Bbase + (size_t)(n0 + r) * K_DIM) + kb + kc;
            CP_ASYNC16(dst, src, 16u);
        }
    };

    const int wm = (wid & 1) * 64;
    const int wn = (wid >> 1) * 32;
    const uint32_t sw = (uint32_t)((lane & 7) << 4);

    float acc[4][4][4];
#pragma unroll
    for (int i = 0; i < 4; i++)
#pragma unroll
        for (int j = 0; j < 4; j++)
#pragma unroll
            for (int k = 0; k < 4; k++) acc[i][j][k] = 0.f;

    uint32_t aBase[4], bBase[2];
#pragma unroll
    for (int mf = 0; mf < 4; mf++) {
        int r = wm + mf * 16 + (lane & 15);
        aBase[mf] = (uint32_t)(r * 128) + ((uint32_t)((lane >> 4) << 4) ^ sw);
    }
#pragma unroll
    for (int np = 0; np < 2; np++) {
        int r = wn + np * 16 + ((lane >> 4) << 3) + (lane & 7);
        bBase[np] = (uint32_t)(r * 128 + 16384) + ((uint32_t)(((lane >> 3) & 1) << 4) ^ sw);
    }

    load_stage(0);
    CP_COMMIT();
    load_stage(1);
    CP_COMMIT();

    for (int it = 0; it < NITER; ++it) {
        CP_WAIT1();
        __syncthreads();
        if (it + 2 < NITER) load_stage(it + 2);
        CP_COMMIT();

        const uint32_t stg = sb + OFF_STAGE + (uint32_t)(it % 3) * STAGE_BYTES;

        uint32_t af[2][4][4];
        uint32_t bf[2][4][2];
#pragma unroll
        for (int mf = 0; mf < 4; mf++)
            LDSM_X4(af[0][mf][0], af[0][mf][1], af[0][mf][2], af[0][mf][3],
                    stg + aBase[mf]);
#pragma unroll
        for (int np = 0; np < 2; np++)
            LDSM_X4(bf[0][2 * np][0], bf[0][2 * np][1],
                    bf[0][2 * np + 1][0], bf[0][2 * np + 1][1],
                    stg + bBase[np]);

#pragma unroll
        for (int ks = 0; ks < 4; ks++) {
            const int cur = ks & 1;
            const int nxt = cur ^ 1;
            if (ks < 3) {
                const uint32_t x = (uint32_t)((ks + 1) << 5);
#pragma unroll
                for (int mf = 0; mf < 4; mf++)
                    LDSM_X4(af[nxt][mf][0], af[nxt][mf][1], af[nxt][mf][2], af[nxt][mf][3],
                            stg + (aBase[mf] ^ x));
#pragma unroll
                for (int np = 0; np < 2; np++)
                    LDSM_X4(bf[nxt][2 * np][0], bf[nxt][2 * np][1],
                            bf[nxt][2 * np + 1][0], bf[nxt][2 * np + 1][1],
                            stg + (bBase[np] ^ x));
            }
#pragma unroll
            for (int mf = 0; mf < 4; mf++)
#pragma unroll
                for (int nf = 0; nf < 4; nf++) {
                    asm volatile(
                        "mma.sync.aligned.m16n8k16.row.col.f32.f16.f16.f32 "
                        "{%0,%1,%2,%3}, {%4,%5,%6,%7}, {%8,%9}, {%0,%1,%2,%3};"
                        : "+f"(acc[mf][nf][0]), "+f"(acc[mf][nf][1]),
                          "+f"(acc[mf][nf][2]), "+f"(acc[mf][nf][3])
                        : "r"(af[cur][mf][0]), "r"(af[cur][mf][1]),
                          "r"(af[cur][mf][2]), "r"(af[cur][mf][3]),
                          "r"(bf[cur][nf][0]), "r"(bf[cur][nf][1]));
                }
        }
    }

    // ---- epilogue ----
    const int lr = lane >> 2;
    const int lc = (lane & 3) * 2;
#pragma unroll
    for (int mf = 0; mf < 4; mf++) {
#pragma unroll
        for (int h = 0; h < 2; h++) {
            int rl = wm + mf * 16 + lr + h * 8;
            int slot = sSlot[rl];
            if (slot < 0) continue;
            if (isUp) {
#pragma unroll
                for (int nf = 0; nf < 4; nf++) {
                    int col = n0 + wn + nf * 8 + lc;
                    float v0 = gelu_exact(acc[mf][nf][h * 2 + 0] + bptr[col]);
                    float v1 = gelu_exact(acc[mf][nf][h * 2 + 1] + bptr[col + 1]);
                    *reinterpret_cast<__half2*>(&g_He[(size_t)slot * H_DIM + col]) =
                        __floats2half2_rn(v0, v1);
                }
            } else {
                float w = g_expW[slot];
                float* orow = outp + (size_t)(slot >> 1) * D_DIM;
#pragma unroll
                for (int nf = 0; nf < 4; nf++) {
                    int col = n0 + wn + nf * 8 + lc;
                    float v0 = acc[mf][nf][h * 2 + 0] + bptr[col];
                    float v1 = acc[mf][nf][h * 2 + 1] + bptr[col + 1];
                    atomicAdd(&orow[col],     w * v0);
                    atomicAdd(&orow[col + 1], w * v1);
                }
            }
        }
    }

    if (isUp) {
        __syncthreads();            // all He stores issued
        if (tid == 0) {
            __threadfence();        // release: He visible before counter bump
            atomicAdd(&g_mtdone[mt], 1);
        }
    }
}

// ---------------- launch ------------------------------------------------------
extern "C" void kernel_launch(void* const* d_in, const int* in_sizes, int n_in,
                              void* d_out, int out_size) {
    const float* x   = (const float*)d_in[0];
    const float* Wr1 = (const float*)d_in[1];
    const float* br1 = (const float*)d_in[2];
    const float* Wr2 = (const float*)d_in[3];
    const float* br2 = (const float*)d_in[4];
    const float* W1  = (const float*)d_in[5];
    const float* b1  = (const float*)d_in[6];
    const float* W2  = (const float*)d_in[7];
    const float* b2  = (const float*)d_in[8];
    float* out = (float*)d_out;

    static cudaStream_t sW = nullptr;
    static cudaEvent_t evFork = nullptr, evW = nullptr;
    if (sW == nullptr) {
        cudaStreamCreateWithFlags(&sW, cudaStreamNonBlocking);
        cudaEventCreateWithFlags(&evFork, cudaEventDisableTiming);
        cudaEventCreateWithFlags(&evW, cudaEventDisableTiming);
        cudaFuncSetAttribute(router_gemm_kernel, cudaFuncAttributeMaxDynamicSharedMemorySize, SMEM_TOTAL);
        cudaFuncSetAttribute(expert_fused_kernel, cudaFuncAttributeMaxDynamicSharedMemorySize, SMEM_TOTAL);
    }

    // Fork: W1/W2 conversion + out zero-fill concurrent with router chain
    cudaEventRecord(evFork, 0);
    cudaStreamWaitEvent(sW, evFork, 0);
    {
        zero_out_kernel<<<T_TOKENS * D_DIM / 4 / 256, 256, 0, sW>>>(out);
        int n4 = E_NUM * H_DIM * D_DIM / 4;
        conv_kernel<<<2 * n4 / 256, 256, 0, sW>>>(W1, W2, n4);
    }
    cudaEventRecord(evW, sW);

    // Router: split -> fused GEMM+logits+top2+fill
    split_kernel<<<((T_TOKENS + R_DIM) * 256) / 256, 256>>>(x, Wr1);
    router_gemm_kernel<<<dim3(R_DIM / 128, 64, 1), 256, SMEM_TOTAL>>>(br1, Wr2, br2);

    // Experts: single fused launch; DOWN overlaps UP's tail via mt counters
    cudaStreamWaitEvent(0, evW, 0);
    expert_fused_kernel<<<UP_CTAS + DN_CTAS, 256, SMEM_TOTAL>>>(b1, b2, out);
}

// round 16
// speedup vs baseline: 1.1714x; 1.1714x over previous
#include <cuda_runtime.h>
#include <cuda_fp16.h>
#include <math.h>
#include <stdint.h>

// Problem constants
#define T_TOKENS 8192
#define D_DIM    1024
#define H_DIM    4096
#define R_DIM    512
#define E_NUM    8
#define SLOTS    (T_TOKENS * 2)
#define MAX_TILES 136
#define KR_DIM   3072   // router split-K: [xh|xh|xl] x [wh|wl|wh] (A stores [xh|xl])
#define XS_STRIDE 2048  // g_xsplit row stride: [xh(1024) | xl(1024)]
#define SEG_CAP  16384  // fixed per-expert perm segment

// ---------------- scratch (device globals; no allocation allowed) ----------
__device__ __half g_xsplit[T_TOKENS * XS_STRIDE];    // [xh|xl]         33MB
__device__ __half g_wr1split[R_DIM * KR_DIM];        // [wh|wl|wh]*32    3MB
__device__ __half g_W1h[E_NUM * H_DIM * D_DIM];      // W1 fp16         67MB
__device__ __half g_W2h[E_NUM * D_DIM * H_DIM];      // W2 fp16         67MB
__device__ __half g_He[SLOTS * H_DIM];               // expert hidden  134MB
__device__ float  g_logits[T_TOKENS * E_NUM];
__device__ float  g_expW[SLOTS];
__device__ int    g_rowdone[64];
__device__ int    g_fillpos[E_NUM];
__device__ int    g_perm[E_NUM * SEG_CAP];

__device__ __forceinline__ float gelu_exact(float x) {
    return 0.5f * x * (1.0f + erff(x * 0.7071067811865476f));
}

__device__ __forceinline__ uint32_t smem_to_u32(const void* p) {
    uint32_t a;
    asm("{ .reg .u64 t; cvta.to.shared.u64 t, %1; cvt.u32.u64 %0, t; }" : "=r"(a) : "l"(p));
    return a;
}
#define CP_ASYNC16(dst, src, sz) \
    asm volatile("cp.async.cg.shared.global [%0], [%1], 16, %2;" \
                 :: "r"(dst), "l"(src), "r"(sz))
#define CP_COMMIT() asm volatile("cp.async.commit_group;" ::: "memory")
#define CP_WAIT1()  asm volatile("cp.async.wait_group 1;" ::: "memory")

#define LDSM_X4(r0, r1, r2, r3, addr) \
    asm volatile("ldmatrix.sync.aligned.m8n8.x4.shared.b16 {%0,%1,%2,%3}, [%4];" \
                 : "=r"(r0), "=r"(r1), "=r"(r2), "=r"(r3) : "r"(addr))

// ---------------- fused converts --------------------------------------------
__global__ void conv_kernel(const float* __restrict__ W1,
                            const float* __restrict__ W2, int n4) {
    int i = blockIdx.x * blockDim.x + threadIdx.x;
    const float* src;
    __half* dst;
    if (i < n4) { src = W1; dst = g_W1h; }
    else        { i -= n4; src = W2; dst = g_W2h; }
    float4 v = reinterpret_cast<const float4*>(src)[i];
    __half2* d2 = reinterpret_cast<__half2*>(dst + (size_t)i * 4);
    d2[0] = __floats2half2_rn(v.x, v.y);
    d2[1] = __floats2half2_rn(v.z, v.w);
}

// zero d_out (poisoned 0xAA by harness; DOWN epilogue accumulates into it)
__global__ void zero_out_kernel(float* __restrict__ out) {
    int i = blockIdx.x * blockDim.x + threadIdx.x;
    reinterpret_cast<float4*>(out)[i] = make_float4(0.f, 0.f, 0.f, 0.f);
}

// x -> [xh|xl] (stride 2048), Wr1*32 -> [wh|wl|wh]; zeroes logits/rowdone/fillpos
__global__ void split_kernel(const float* __restrict__ x,
                             const float* __restrict__ w) {
    if (blockIdx.x < 64) {
        int zi = blockIdx.x * 256 + threadIdx.x;
        reinterpret_cast<float4*>(g_logits)[zi] = make_float4(0.f, 0.f, 0.f, 0.f);
    } else if (blockIdx.x == 64) {
        if (threadIdx.x < 64) g_rowdone[threadIdx.x] = 0;
        else if (threadIdx.x < 64 + E_NUM) g_fillpos[threadIdx.x - 64] = 0;
    }
    int i = blockIdx.x * blockDim.x + threadIdx.x;
    int row = i >> 8;
    int c4 = (i & 255) * 4;
    __half h[4], l[4];
    if (row < T_TOKENS) {
        float4 v = reinterpret_cast<const float4*>(x)[i];
        float vv[4] = {v.x, v.y, v.z, v.w};
#pragma unroll
        for (int q = 0; q < 4; q++) {
            h[q] = __float2half_rn(vv[q]);
            l[q] = __float2half_rn(vv[q] - __half2float(h[q]));
        }
        __half* r = g_xsplit + (size_t)row * XS_STRIDE + c4;
        __half2 h01 = __halves2half2(h[0], h[1]), h23 = __halves2half2(h[2], h[3]);
        __half2 l01 = __halves2half2(l[0], l[1]), l23 = __halves2half2(l[2], l[3]);
        ((__half2*)(r))[0] = h01;        ((__half2*)(r))[1] = h23;
        ((__half2*)(r + 1024))[0] = l01; ((__half2*)(r + 1024))[1] = l23;
    } else {
        int wr = row - T_TOKENS;
        float4 v = reinterpret_cast<const float4*>(w)[(size_t)wr * 256 + (c4 >> 2)];
        float vv[4] = {v.x * 32.f, v.y * 32.f, v.z * 32.f, v.w * 32.f};
#pragma unroll
        for (int q = 0; q < 4; q++) {
            h[q] = __float2half_rn(vv[q]);
            l[q] = __float2half_rn(vv[q] - __half2float(h[q]));
        }
        __half* r = g_wr1split + (size_t)wr * KR_DIM + c4;
        __half2 h01 = __halves2half2(h[0], h[1]), h23 = __halves2half2(h[2], h[3]);
        __half2 l01 = __halves2half2(l[0], l[1]), l23 = __halves2half2(l[2], l[3]);
        ((__half2*)(r))[0] = h01;        ((__half2*)(r))[1] = h23;
        ((__half2*)(r + 1024))[0] = l01; ((__half2*)(r + 1024))[1] = l23;
        ((__half2*)(r + 2048))[0] = h01; ((__half2*)(r + 2048))[1] = h23;
    }
}

// ---------------- unified HMMA GEMM -----------------------------------------
// MODE 0: router  A'B'^T -> gelu -> partial logits -> closing CTA top2/fill
//         A K-segments remapped: it<32 -> xh block, it>=32 -> xl block
// MODE 1: UP      He = gelu(xh@W1[e]^T + b1[e]) fp16, gathered (token=slot>>1)
// MODE 2: DOWN    out[token] += w_slot * (He@W2[e]^T + b2)  (fused combine)
// CTA tile 128x128, K-chunk 64, 3-stage cp.async, 256 thr, 2 CTAs/SM.
#define OFF_STAGE  8192
#define STAGE_BYTES 32768
#define SMEM_TOTAL (OFF_STAGE + 3 * STAGE_BYTES)

template <int MODE>
__global__ void __launch_bounds__(256, 2) moe_gemm_kernel(
    const float* __restrict__ bias_in,
    const float* __restrict__ Wr2,
    const float* __restrict__ br2,
    float* __restrict__ outp)
{
    constexpr int K_DIM = (MODE == 0) ? KR_DIM : (MODE == 1 ? 1024 : 4096);
    constexpr int A_STRIDE = (MODE == 2) ? 4096 : XS_STRIDE;
    constexpr int NITER = K_DIM / 64;

    extern __shared__ char smem[];
    __shared__ int sOld;
    const uint32_t sb = smem_to_u32(smem);
    int* sSlot = (int*)smem;
    float* sW2 = (float*)smem;
    const int tid = threadIdx.x;
    const int wid = tid >> 5;
    const int lane = tid & 31;
    const int n0 = blockIdx.x * 128;

    int m0 = 0, eIdx = 0;
    if (MODE == 0) {
        m0 = blockIdx.y * 128;
        int f = tid * 4;
        int e = f >> 7;
        int j = f & 127;
        float4 v = *reinterpret_cast<const float4*>(&Wr2[e * R_DIM + n0 + j]);
        *reinterpret_cast<float4*>(&sW2[f]) = v;
    } else {
        int mt = blockIdx.y;
        eIdx = -1;
        int pos0 = 0, segEnd = 0, tS = 0;
#pragma unroll
        for (int e = 0; e < E_NUM; e++) {
            int cnt = g_fillpos[e];
            int tiles = (cnt + 127) >> 7;
            if (eIdx < 0 && mt >= tS && mt < tS + tiles) {
                eIdx = e;
                pos0 = e * SEG_CAP + (mt - tS) * 128;
                segEnd = e * SEG_CAP + cnt;
            }
            tS += tiles;
        }
        if (eIdx < 0) return;
        if (tid < 128) {
            int p = pos0 + tid;
            sSlot[tid] = (p < segEnd) ? g_perm[p] : -1;
        }
    }
    __syncthreads();

    const __half* Abase = (MODE == 2) ? g_He : g_xsplit;
    const __half* Bbase;
    const float* bptr;
    if (MODE == 0)      { Bbase = g_wr1split;                              bptr = bias_in; }
    else if (MODE == 1) { Bbase = g_W1h + (size_t)eIdx * (H_DIM * D_DIM);  bptr = bias_in + eIdx * H_DIM; }
    else                { Bbase = g_W2h + (size_t)eIdx * (D_DIM * H_DIM);  bptr = bias_in + eIdx * D_DIM; }

    int aRow[4];
    uint32_t aSz[4];
#pragma unroll
    for (int j = 0; j < 4; j++) {
        int r = (tid + j * 256) >> 3;
        aSz[j] = 16;
        if (MODE == 0) aRow[j] = m0 + r;
        else {
            int slot = sSlot[r];
            if (slot < 0) { aRow[j] = 0; aSz[j] = 0; }
            else aRow[j] = (MODE == 1) ? (slot >> 1) : slot;
        }
    }

    auto load_stage = [&](int it) {
        const uint32_t so = sb + OFF_STAGE + (uint32_t)(it % 3) * STAGE_BYTES;
        // A byte offset along K: MODE 0 remaps [xh|xh|xl] onto [xh|xl] storage
        size_t kbA;
        if (MODE == 0) kbA = (it < 32) ? (size_t)((it & 15) * 128)
                                       : (size_t)(2048 + (it - 32) * 128);
        else           kbA = (size_t)it * 128;
        const size_t kbB = (size_t)it * 128;
#pragma unroll
        for (int j = 0; j < 4; j++) {
            int c = tid + j * 256;
            int r = c >> 3;
            int kc = (c & 7) << 4;
            uint32_t dst = so + (uint32_t)(r * 128 + (kc ^ ((r & 7) << 4)));
            const char* src = (const char*)(Abase + (size_t)aRow[j] * A_STRIDE) + kbA + kc;
            CP_ASYNC16(dst, src, aSz[j]);
        }
#pragma unroll
        for (int j = 0; j < 4; j++) {
            int c = tid + j * 256;
            int r = c >> 3;
            int kc = (c & 7) << 4;
            uint32_t dst = so + 16384u + (uint32_t)(r * 128 + (kc ^ ((r & 7) << 4)));
            const char* src = (const char*)(Bbase + (size_t)(n0 + r) * K_DIM) + kbB + kc;
            CP_ASYNC16(dst, src, 16u);
        }
    };

    const int wm = (wid & 1) * 64;
    const int wn = (wid >> 1) * 32;
    const uint32_t sw = (uint32_t)((lane & 7) << 4);

    float acc[4][4][4];
#pragma unroll
    for (int i = 0; i < 4; i++)
#pragma unroll
        for (int j = 0; j < 4; j++)
#pragma unroll
            for (int k = 0; k < 4; k++) acc[i][j][k] = 0.f;

    // lane-invariant LDSM base offsets within a stage (ks=0); addr(ks)=base^(ks<<5)
    uint32_t aBase[4], bBase[2];
#pragma unroll
    for (int mf = 0; mf < 4; mf++) {
        int r = wm + mf * 16 + (lane & 15);
        aBase[mf] = (uint32_t)(r * 128) + ((uint32_t)((lane >> 4) << 4) ^ sw);
    }
#pragma unroll
    for (int np = 0; np < 2; np++) {
        int r = wn + np * 16 + ((lane >> 4) << 3) + (lane & 7);
        bBase[np] = (uint32_t)(r * 128 + 16384) + ((uint32_t)(((lane >> 3) & 1) << 4) ^ sw);
    }

    load_stage(0);
    CP_COMMIT();
    load_stage(1);
    CP_COMMIT();

    for (int it = 0; it < NITER; ++it) {
        CP_WAIT1();
        __syncthreads();
        if (it + 2 < NITER) load_stage(it + 2);
        CP_COMMIT();   // unconditional: keeps pending-group invariant on the tail

        const uint32_t stg = sb + OFF_STAGE + (uint32_t)(it % 3) * STAGE_BYTES;

        uint32_t af[2][4][4];
        uint32_t bf[2][4][2];
        // prefetch ks=0 fragments
#pragma unroll
        for (int mf = 0; mf < 4; mf++)
            LDSM_X4(af[0][mf][0], af[0][mf][1], af[0][mf][2], af[0][mf][3],
                    stg + aBase[mf]);
#pragma unroll
        for (int np = 0; np < 2; np++)
            LDSM_X4(bf[0][2 * np][0], bf[0][2 * np][1],
                    bf[0][2 * np + 1][0], bf[0][2 * np + 1][1],
                    stg + bBase[np]);

#pragma unroll
        for (int ks = 0; ks < 4; ks++) {
            const int cur = ks & 1;
            const int nxt = cur ^ 1;
            if (ks < 3) {
                const uint32_t x = (uint32_t)((ks + 1) << 5);
#pragma unroll
                for (int mf = 0; mf < 4; mf++)
                    LDSM_X4(af[nxt][mf][0], af[nxt][mf][1], af[nxt][mf][2], af[nxt][mf][3],
                            stg + (aBase[mf] ^ x));
#pragma unroll
                for (int np = 0; np < 2; np++)
                    LDSM_X4(bf[nxt][2 * np][0], bf[nxt][2 * np][1],
                            bf[nxt][2 * np + 1][0], bf[nxt][2 * np + 1][1],
                            stg + (bBase[np] ^ x));
            }
#pragma unroll
            for (int mf = 0; mf < 4; mf++)
#pragma unroll
                for (int nf = 0; nf < 4; nf++) {
                    asm volatile(
                        "mma.sync.aligned.m16n8k16.row.col.f32.f16.f16.f32 "
                        "{%0,%1,%2,%3}, {%4,%5,%6,%7}, {%8,%9}, {%0,%1,%2,%3};"
                        : "+f"(acc[mf][nf][0]), "+f"(acc[mf][nf][1]),
                          "+f"(acc[mf][nf][2]), "+f"(acc[mf][nf][3])
                        : "r"(af[cur][mf][0]), "r"(af[cur][mf][1]),
                          "r"(af[cur][mf][2]), "r"(af[cur][mf][3]),
                          "r"(bf[cur][nf][0]), "r"(bf[cur][nf][1]));
                }
        }
    }

    // ---- epilogue ----
    const int lr = lane >> 2;
    const int lc = (lane & 3) * 2;
    if (MODE == 0) {
#pragma unroll
        for (int mf = 0; mf < 4; mf++) {
#pragma unroll
            for (int h = 0; h < 2; h++) {
                int rl = wm + mf * 16 + lr + h * 8;
                float part[E_NUM];
#pragma unroll
                for (int e = 0; e < E_NUM; e++) part[e] = 0.f;
#pragma unroll
                for (int nf = 0; nf < 4; nf++) {
                    int colL = wn + nf * 8 + lc;
                    float v0 = gelu_exact(acc[mf][nf][h * 2 + 0] * 0.03125f + bptr[n0 + colL]);
                    float v1 = gelu_exact(acc[mf][nf][h * 2 + 1] * 0.03125f + bptr[n0 + colL + 1]);
#pragma unroll
                    for (int e = 0; e < E_NUM; e++)
                        part[e] += v0 * sW2[e * 128 + colL] + v1 * sW2[e * 128 + colL + 1];
                }
#pragma unroll
                for (int e = 0; e < E_NUM; e++) {
                    part[e] += __shfl_xor_sync(0xffffffffu, part[e], 1);
                    part[e] += __shfl_xor_sync(0xffffffffu, part[e], 2);
                }
                if ((lane & 3) == 0) {
#pragma unroll
                    for (int e = 0; e < E_NUM; e++)
                        atomicAdd(&g_logits[(size_t)(m0 + rl) * E_NUM + e], part[e]);
                }
            }
        }
        __syncthreads();
        if (tid == 0) {
            __threadfence();
            sOld = atomicAdd(&g_rowdone[blockIdx.y], 1);
        }
        __syncthreads();
        if (sOld == 3 && tid < 128) {
            __threadfence();
            int t = m0 + tid;
            float l[E_NUM];
#pragma unroll
            for (int e = 0; e < E_NUM; e++)
                l[e] = __ldcg(&g_logits[(size_t)t * E_NUM + e]) + br2[e];
            int i0 = 0; float v0 = l[0];
#pragma unroll
            for (int e = 1; e < E_NUM; e++) if (l[e] > v0) { v0 = l[e]; i0 = e; }
            int i1 = -1; float v1 = -1e30f;
#pragma unroll
            for (int e = 0; e < E_NUM; e++) if (e != i0 && l[e] > v1) { v1 = l[e]; i1 = e; }
            float s = 0.f;
#pragma unroll
            for (int e = 0; e < E_NUM; e++) s += expf(l[e] - v0);
            g_expW[2 * t]     = 1.f / s;
            g_expW[2 * t + 1] = expf(v1 - v0) / s;
            int r0 = atomicAdd(&g_fillpos[i0], 1);
            g_perm[i0 * SEG_CAP + r0] = 2 * t;
            int r1 = atomicAdd(&g_fillpos[i1], 1);
            g_perm[i1 * SEG_CAP + r1] = 2 * t + 1;
        }
        return;
    }

#pragma unroll
    for (int mf = 0; mf < 4; mf++) {
#pragma unroll
        for (int h = 0; h < 2; h++) {
            int rl = wm + mf * 16 + lr + h * 8;
            int slot = sSlot[rl];
            if (slot < 0) continue;
            if (MODE == 1) {
#pragma unroll
                for (int nf = 0; nf < 4; nf++) {
                    int col = n0 + wn + nf * 8 + lc;
                    float v0 = gelu_exact(acc[mf][nf][h * 2 + 0] + bptr[col]);
                    float v1 = gelu_exact(acc[mf][nf][h * 2 + 1] + bptr[col + 1]);
                    *reinterpret_cast<__half2*>(&g_He[(size_t)slot * H_DIM + col]) =
                        __floats2half2_rn(v0, v1);
                }
            } else {
                // fused combine: out[token] += w_slot * (y + b2)
                float w = g_expW[slot];
                float* orow = outp + (size_t)(slot >> 1) * D_DIM;
#pragma unroll
                for (int nf = 0; nf < 4; nf++) {
                    int col = n0 + wn + nf * 8 + lc;
                    float v0 = acc[mf][nf][h * 2 + 0] + bptr[col];
                    float v1 = acc[mf][nf][h * 2 + 1] + bptr[col + 1];
                    atomicAdd(&orow[col],     w * v0);
                    atomicAdd(&orow[col + 1], w * v1);
                }
            }
        }
    }
}

// ---------------- launch ------------------------------------------------------
extern "C" void kernel_launch(void* const* d_in, const int* in_sizes, int n_in,
                              void* d_out, int out_size) {
    const float* x   = (const float*)d_in[0];
    const float* Wr1 = (const float*)d_in[1];
    const float* br1 = (const float*)d_in[2];
    const float* Wr2 = (const float*)d_in[3];
    const float* br2 = (const float*)d_in[4];
    const float* W1  = (const float*)d_in[5];
    const float* b1  = (const float*)d_in[6];
    const float* W2  = (const float*)d_in[7];
    const float* b2  = (const float*)d_in[8];
    float* out = (float*)d_out;

    static cudaStream_t sW = nullptr;
    static cudaEvent_t evFork = nullptr, evW = nullptr;
    if (sW == nullptr) {
        cudaStreamCreateWithFlags(&sW, cudaStreamNonBlocking);
        cudaEventCreateWithFlags(&evFork, cudaEventDisableTiming);
        cudaEventCreateWithFlags(&evW, cudaEventDisableTiming);
        cudaFuncSetAttribute(moe_gemm_kernel<0>, cudaFuncAttributeMaxDynamicSharedMemorySize, SMEM_TOTAL);
        cudaFuncSetAttribute(moe_gemm_kernel<1>, cudaFuncAttributeMaxDynamicSharedMemorySize, SMEM_TOTAL);
        cudaFuncSetAttribute(moe_gemm_kernel<2>, cudaFuncAttributeMaxDynamicSharedMemorySize, SMEM_TOTAL);
    }

    // Fork: W1/W2 conversion + out zero-fill concurrent with router chain
    cudaEventRecord(evFork, 0);
    cudaStreamWaitEvent(sW, evFork, 0);
    {
        zero_out_kernel<<<T_TOKENS * D_DIM / 4 / 256, 256, 0, sW>>>(out);
        int n4 = E_NUM * H_DIM * D_DIM / 4;
        conv_kernel<<<2 * n4 / 256, 256, 0, sW>>>(W1, W2, n4);
    }
    cudaEventRecord(evW, sW);

    // Router: split -> fused GEMM+logits+top2+fill
    split_kernel<<<((T_TOKENS + R_DIM) * 256) / 256, 256>>>(x, Wr1);
    moe_gemm_kernel<0><<<dim3(R_DIM / 128, 64, 1), 256, SMEM_TOTAL>>>(br1, Wr2, br2, nullptr);

    // Experts (DOWN writes final output via fused weighted accumulation)
    cudaStreamWaitEvent(0, evW, 0);
    moe_gemm_kernel<1><<<dim3(H_DIM / 128, MAX_TILES, 1), 256, SMEM_TOTAL>>>(b1, nullptr, nullptr, nullptr);
    moe_gemm_kernel<2><<<dim3(D_DIM / 128, MAX_TILES, 1), 256, SMEM_TOTAL>>>(b2, nullptr, nullptr, out);
}